// round 9
// baseline (speedup 1.0000x reference)
#include <cuda_runtime.h>
#include <cuda_fp16.h>
#include <math.h>

// ---------------- problem constants ----------------
#define HH      1024
#define WW      1024
#define NPIX    (HH * WW)
#define KK      8
#define WS      11
#define RAD     5

// ---------------- main tiling: 64 x 32 tiles, 512 threads ----------------
#define TW       64
#define TH       32
#define HTW      74            // TW + 2*RAD
#define HTH      42            // TH + 2*RAD
#define HT       (HTW * HTH)   // 3108
#define NT2      512
#define NLOAD    7             // ceil(HT / NT2)
#define VBW      75            // vb row stride (float4 units)
#define MAINB    512           // (1024/64)*(1024/32)

// smem layout (bytes), 16B-aligned
#define OFF_F4    0                       // float4[HT]      49728
#define OFF_VB4   49728                   // float4[32*75]   38400
#define SMEM_TOTAL 88128

struct GW { float w[WS]; };

// ---------------- scratch (static device globals; no allocation) ----------------
__device__ uint2 g_muY2[KK * NPIX / 4];   // per-pixel muYs (shifted) as 4 halfs (16MB)
__device__ uint2 g_cs2[NPIX / 4];         // per-pixel cs_map as 4 halfs (2MB)
__device__ uint2 g_mx2[NPIX / 4];         // per-pixel muXs (shifted) as 4 halfs (2MB)
__device__ float g_lY_part[KK * MAINB];
__device__ float g_lG[KK];
__device__ float g_q_part[MAINB];
__device__ int   g_done1 = 0;
__device__ int   g_done2 = 0;

// ======================= separable blur helpers =======================
// Vertical: 6 consecutive output rows per task, 16 taps -> 2.67 loads/output.
__device__ __forceinline__ void vpass6(const float4* __restrict__ f4,
                                       float4* __restrict__ vb4,
                                       const float* gw, int tid) {
    if (tid < 444) {
        int g = tid / HTW, c = tid - g * HTW;
        int r0 = g * 6;
        float ax[6], ay[6], az[6];
#pragma unroll
        for (int i = 0; i < 6; i++) { ax[i] = 0.f; ay[i] = 0.f; az[i] = 0.f; }
        const float4* p = f4 + r0 * HTW + c;
#pragma unroll
        for (int j = 0; j < 16; j++) {
            if (r0 + j < HTH) {
                float4 v = p[j * HTW];
#pragma unroll
                for (int i = 0; i < 6; i++) {
                    if (i <= j && j - i <= 10) {
                        float gg = gw[j - i];
                        ax[i] += gg * v.x; ay[i] += gg * v.y; az[i] += gg * v.z;
                    }
                }
            }
        }
#pragma unroll
        for (int i = 0; i < 6; i++) {
            int r = r0 + i;
            if (r < TH) vb4[r * VBW + c] = make_float4(ax[i], ay[i], az[i], 0.f);
        }
    }
}

// Horizontal: lane = row (stride 75 float4 -> banks 12*l mod 32, conflict-free),
// 4 cols/thread.
__device__ __forceinline__ void hpass(const float4* __restrict__ vb4,
                                      const float* gw, int row, int x0, float3* out) {
    float ax[4], ay[4], az[4];
#pragma unroll
    for (int i = 0; i < 4; i++) { ax[i] = 0.f; ay[i] = 0.f; az[i] = 0.f; }
    const float4* p = vb4 + row * VBW + x0;
#pragma unroll
    for (int j = 0; j < 14; j++) {
        float4 v = p[j];
#pragma unroll
        for (int i = 0; i < 4; i++) {
            if (i <= j && j - i <= 10) {
                float gg = gw[j - i];
                ax[i] += gg * v.x; ay[i] += gg * v.y; az[i] += gg * v.z;
            }
        }
    }
#pragma unroll
    for (int i = 0; i < 4; i++) out[i] = make_float3(ax[i], ay[i], az[i]);
}

// Pack-write: load bunch k tile (shifted), build (s, s², s·o', 0) field.
__device__ __forceinline__ void pack_write(const float* __restrict__ bb,
                                           const int* goff, const __half2* h01,
                                           const __half2* h2p,
                                           float4* __restrict__ s_f4, int tid) {
#pragma unroll
    for (int i = 0; i < NLOAD; i++) {
        int e = tid + i * NT2;
        if (e < HT) {
            int o = goff[i];
            float v0 = -0.5f, v1 = -0.5f, v2 = -0.5f;
            if (o >= 0) {
                v0 = bb[o] - 0.5f; v1 = bb[NPIX + o] - 0.5f; v2 = bb[2 * NPIX + o] - 0.5f;
            }
            float2 o01 = __half22float2(h01[i]);
            float  o2  = __half2float((i & 1) ? __high2half(h2p[i >> 1])
                                              : __low2half(h2p[i >> 1]));
            s_f4[e] = make_float4((v0 + v1 + v2) * (1.f / 3.f),
                                  (v0 * v0 + v1 * v1 + v2 * v2) * (1.f / 3.f),
                                  (v0 * o01.x + v1 * o01.y + v2 * o2) * (1.f / 3.f), 0.f);
        }
    }
}

__device__ __forceinline__ uint2 pack4h(float a, float b, float c, float d) {
    __half2 p0 = __floats2half2_rn(a, b);
    __half2 p1 = __floats2half2_rn(c, d);
    uint2 u;
    u.x = *(const unsigned int*)&p0;
    u.y = *(const unsigned int*)&p1;
    return u;
}

// ======================= k1: stats pass =======================
// Shifted domain v' = v - 0.5 (exact; reference zero-pads raw => padded v' = -0.5).
__global__ __launch_bounds__(NT2, 2) void mef_stats_k(
    const float* __restrict__ img,
    const float* __restrict__ bunch,
    float* __restrict__ patch_out,
    GW gwp)
{
    extern __shared__ char sm[];
    float4* s_f4  = (float4*)(sm + OFF_F4);
    float4* s_vb4 = (float4*)(sm + OFF_VB4);
    __shared__ float s_ly[16 * KK];     // per-warp per-k lY partials
    __shared__ float qw[16];
    const float* gw = gwp.w;

    int tid = threadIdx.x;
    int lane = tid & 31;
    int wid = tid >> 5;
    int row = tid & 31;          // hpass: output row
    int x0c = (tid >> 5) * 4;    // hpass: 4 consecutive output cols
    int bx = blockIdx.x, by = blockIdx.y;
    int T  = by * gridDim.x + bx;    // tile id 0..511
    int gx0 = bx * TW - RAD, gy0 = by * TH - RAD;

    // per-thread halo state: global offsets + output-image channels (half regs)
    int goff[NLOAD];
    __half2 h01[NLOAD];          // (o0', o1')
    __half2 h2p[4];              // o2' packed pairs
#pragma unroll
    for (int i = 0; i < 4; i++) h2p[i] = __halves2half2(__float2half(0.f), __float2half(0.f));

#pragma unroll
    for (int i = 0; i < NLOAD; i++) {
        int e = tid + i * NT2;
        float o0 = -0.5f, o1 = -0.5f, o2 = -0.5f;
        int o = -2;
        if (e < HT) {
            int hy = e / HTW, hx = e - hy * HTW;
            int gy = gy0 + hy, gx = gx0 + hx;
            o = (((unsigned)gy < HH) && ((unsigned)gx < WW)) ? gy * WW + gx : -1;
            if (o >= 0) {
                o0 = img[o] - 0.5f; o1 = img[NPIX + o] - 0.5f; o2 = img[2 * NPIX + o] - 0.5f;
            }
            s_f4[e] = make_float4((o0 + o1 + o2) * (1.f / 3.f),
                                  (o0 * o0 + o1 * o1 + o2 * o2) * (1.f / 3.f), 0.f, 0.f);
        }
        goff[i] = o;
        h01[i] = __floats2half2_rn(o0, o1);
        __half h2v = __float2half_rn(o2);
        if (i & 1) h2p[i >> 1] = __halves2half2(__low2half(h2p[i >> 1]), h2v);
        else       h2p[i >> 1] = __halves2half2(h2v, __high2half(h2p[i >> 1]));
    }
    __syncthreads();

    vpass6(s_f4, s_vb4, gw, tid);
    __syncthreads();                 // vb ready; pack free
    float3 xo[4];
    hpass(s_vb4, gw, row, x0c, xo);
    float muXs[4], sX2[4];
#pragma unroll
    for (int i = 0; i < 4; i++) { muXs[i] = xo[i].x; sX2[i] = xo[i].y - muXs[i] * muXs[i]; }

    // write pack for k=0 while other warps still in hpass (same barrier interval)
    pack_write(bunch, goff, h01, h2p, s_f4, tid);
    __syncthreads();                 // pack(0) ready; vb consumed

    float best[4], bestXY[4];
    int pidx[4];
#pragma unroll
    for (int i = 0; i < 4; i++) { best[i] = -1e30f; bestXY[i] = 0.f; pidx[i] = 0; }

    for (int k = 0; k < KK; k++) {
        vpass6(s_f4, s_vb4, gw, tid);
        __syncthreads();             // vb ready; pack free
        float3 yo[4];
        hpass(s_vb4, gw, row, x0c, yo);

#pragma unroll
        for (int i = 0; i < 4; i++) {
            float muYs = yo[i].x;
            float sY2 = yo[i].y - muYs * muYs;
            float sXY = yo[i].z - muXs[i] * muYs;
            if (sY2 > best[i]) { best[i] = sY2; bestXY[i] = sXY; pidx[i] = k; }
        }
        // store muYs for blend pass (half, tile-private coalesced layout)
        g_muY2[(size_t)(T * KK + k) * NT2 + tid] =
            pack4h(yo[0].x, yo[1].x, yo[2].x, yo[3].x);
        // per-warp lY partial (exact: tiles partition image)
        float lsum = yo[0].x + yo[1].x + yo[2].x + yo[3].x;
#pragma unroll
        for (int o = 16; o > 0; o >>= 1) lsum += __shfl_xor_sync(0xffffffffu, lsum, o);
        if (lane == 0) s_ly[wid * KK + k] = lsum;

        // prefetch + pack next exposure, overlapping hpass/stat issue stream
        if (k < KK - 1)
            pack_write(bunch + (size_t)(3 * (k + 1)) * NPIX, goff, h01, h2p, s_f4, tid);
        __syncthreads();             // pack(k+1) ready; vb consumed; s_ly visible
    }

    // ---- epilogue ----
    // lY partials: fold 16 warps per k (8 threads, deterministic serial order)
    if (tid < KK) {
        float v = 0.f;
#pragma unroll
        for (int w = 0; w < 16; w++) v += s_ly[w * KK + tid];
        g_lY_part[tid * MAINB + T] = v;
    }

    // cs + muXs (half) and patch staging
    float* sidx = (float*)s_vb4;   // staging: 32 x 64 floats
    float csv[4];
#pragma unroll
    for (int i = 0; i < 4; i++) {
        csv[i] = (2.f * bestXY[i] + 9e-4f) /
                 fmaxf(sX2[i] + best[i] + 9e-4f, 1e-6f);   // C2 = 0.03^2
        sidx[row * 64 + x0c + i] = (float)pidx[i];
    }
    g_cs2[(size_t)T * NT2 + tid] = pack4h(csv[0], csv[1], csv[2], csv[3]);
    g_mx2[(size_t)T * NT2 + tid] = pack4h(muXs[0], muXs[1], muXs[2], muXs[3]);

    __syncthreads();
    if (patch_out) {
        // scalar stores: patch_out base is only 4B-aligned (out + 1).
        int px = tid * 4;
        int rr = px >> 6, cc = px & 63;
        float* dst = &patch_out[(by * TH + rr) * WW + bx * TW + cc];
        const float* src = &sidx[px];
        dst[0] = src[0]; dst[1] = src[1]; dst[2] = src[2]; dst[3] = src[3];
    }

    // ---- last block: fold lY partials -> lG ----
    __shared__ int isLast;
    if (tid == 0) {
        __threadfence();
        isLast = (atomicAdd(&g_done1, 1) == MAINB - 1);
    }
    __syncthreads();
    if (isLast) {
        __threadfence();
        for (int k = 0; k < KK; k++) {
            float s = g_lY_part[k * MAINB + tid];     // MAINB == NT2 == 512
#pragma unroll
            for (int o = 16; o > 0; o >>= 1) s += __shfl_xor_sync(0xffffffffu, s, o);
            if (lane == 0) qw[wid] = s;
            __syncthreads();
            if (tid < 16) {
                float v = qw[tid];
                v += __shfl_xor_sync(0x0000ffffu, v, 8);
                v += __shfl_xor_sync(0x0000ffffu, v, 4);
                v += __shfl_xor_sync(0x0000ffffu, v, 2);
                v += __shfl_xor_sync(0x0000ffffu, v, 1);
                if (tid == 0) {
                    double d = (double)v / (double)NPIX;   // = mean(muYs) = lY - 0.5
                    g_lG[k] = (float)exp(-(d * d) / 0.08); // DENOM_G = 2*0.2^2
                }
            }
            __syncthreads();
        }
        if (tid == 0) g_done1 = 0;   // self-reset for next graph replay
    }
}

// ======================= k2: luminance blend + q =======================
__global__ __launch_bounds__(NT2) void mef_blend_k(float* __restrict__ q_out) {
    __shared__ float s_lG[KK];
    __shared__ float qw[16];
    int tid = threadIdx.x;
    int lane = tid & 31, wid = tid >> 5;
    int T = blockIdx.x;

    if (tid < KK) s_lG[tid] = g_lG[tid];
    __syncthreads();

    float num[4], den[4];
#pragma unroll
    for (int i = 0; i < 4; i++) { num[i] = 0.f; den[i] = 0.f; }

#pragma unroll
    for (int k = 0; k < KK; k++) {
        uint2 u = g_muY2[(size_t)(T * KK + k) * NT2 + tid];
        __half2 pa = *(const __half2*)&u.x;
        __half2 pb = *(const __half2*)&u.y;
        float2 f0 = __half22float2(pa);
        float2 f1 = __half22float2(pb);
        float m[4] = {f0.x, f0.y, f1.x, f1.y};
        float lGk = s_lG[k];
#pragma unroll
        for (int i = 0; i < 4; i++) {
            float wgt = lGk * __expf(-(m[i] * m[i]) * (1.f / 0.08f));   // DENOM_L
            num[i] += wgt * (m[i] + 0.5f);
            den[i] += wgt;
        }
    }

    uint2 cu = g_cs2[(size_t)T * NT2 + tid];
    uint2 mu = g_mx2[(size_t)T * NT2 + tid];
    float2 c0 = __half22float2(*(const __half2*)&cu.x);
    float2 c1 = __half22float2(*(const __half2*)&cu.y);
    float2 x0 = __half22float2(*(const __half2*)&mu.x);
    float2 x1 = __half22float2(*(const __half2*)&mu.y);
    float cs[4] = {c0.x, c0.y, c1.x, c1.y};
    float mx[4] = {x0.x, x0.y, x1.x, x1.y};

    float qsum = 0.f;
#pragma unroll
    for (int i = 0; i < 4; i++) {
        float muX  = mx[i] + 0.5f;
        float muYb = num[i] / den[i];
        float l = (2.f * muX * muYb + 1e-4f) /
                  fmaxf(muX * muX + muYb * muYb + 1e-4f, 1e-6f);   // C1 = 0.01^2
        qsum += l * cs[i];
    }

#pragma unroll
    for (int o = 16; o > 0; o >>= 1) qsum += __shfl_xor_sync(0xffffffffu, qsum, o);
    if (lane == 0) qw[wid] = qsum;
    __syncthreads();
    if (tid < 16) {
        float v = qw[tid];
        v += __shfl_xor_sync(0x0000ffffu, v, 8);
        v += __shfl_xor_sync(0x0000ffffu, v, 4);
        v += __shfl_xor_sync(0x0000ffffu, v, 2);
        v += __shfl_xor_sync(0x0000ffffu, v, 1);
        if (tid == 0) g_q_part[T] = v;
    }

    __shared__ int isLast;
    if (tid == 0) {
        __threadfence();
        isLast = (atomicAdd(&g_done2, 1) == MAINB - 1);
    }
    __syncthreads();
    if (isLast) {
        __threadfence();
        float s = g_q_part[tid];          // MAINB == NT2 == 512
#pragma unroll
        for (int o = 16; o > 0; o >>= 1) s += __shfl_xor_sync(0xffffffffu, s, o);
        if (lane == 0) qw[wid] = s;
        __syncthreads();
        if (tid < 16) {
            float v = qw[tid];
            v += __shfl_xor_sync(0x0000ffffu, v, 8);
            v += __shfl_xor_sync(0x0000ffffu, v, 4);
            v += __shfl_xor_sync(0x0000ffffu, v, 2);
            v += __shfl_xor_sync(0x0000ffffu, v, 1);
            if (tid == 0) {
                if (q_out) q_out[0] = v / (float)NPIX;
                g_done2 = 0;
            }
        }
    }
}

// ---------------- launch ----------------
extern "C" void kernel_launch(void* const* d_in, const int* in_sizes, int n_in,
                              void* d_out, int out_size) {
    const float* a = (const float*)d_in[0];
    const float* b = (const float*)d_in[1];
    const float* img;
    const float* bunch;
    if (in_sizes[0] > in_sizes[1]) { bunch = a; img = b; }
    else                           { img = a;  bunch = b; }

    float* out = (float*)d_out;
    float* qdst = nullptr;
    float* patch = nullptr;
    if (out_size >= NPIX + 1)      { qdst = out; patch = out + 1; }
    else if (out_size == NPIX)     { patch = out; }
    else                           { qdst = out; }

    // host-side double-precision gaussian window
    GW gwp;
    {
        double t[WS], s = 0.0;
        double sg = (double)WS / 6.0;
        for (int i = 0; i < WS; i++) {
            double d = (double)(i - RAD);
            t[i] = exp(-(d * d) / (2.0 * sg * sg));
            s += t[i];
        }
        for (int i = 0; i < WS; i++) gwp.w[i] = (float)(t[i] / s);
    }

    static bool attr_set = false;
    if (!attr_set) {
        cudaFuncSetAttribute(mef_stats_k, cudaFuncAttributeMaxDynamicSharedMemorySize, SMEM_TOTAL);
        attr_set = true;
    }

    mef_stats_k<<<dim3(WW / TW, HH / TH), NT2, SMEM_TOTAL>>>(img, bunch, patch, gwp);
    mef_blend_k<<<MAINB, NT2>>>(qdst);
}

// round 10
// speedup vs baseline: 1.0414x; 1.0414x over previous
#include <cuda_runtime.h>
#include <cuda_fp16.h>
#include <math.h>

// ---------------- problem constants ----------------
#define HH      1024
#define WW      1024
#define NPIX    (HH * WW)
#define KK      8
#define WS      11
#define RAD     5

// ---------------- main tiling: 64 x 64 tiles, 1024 threads, 1 block/SM ----------------
#define TW       64
#define TH       64
#define HTW      74            // TW + 2*RAD
#define HTH      74            // TH + 2*RAD
#define HT       (HTW * HTH)   // 5476
#define NT2      1024
#define NLOAD    6             // ceil(HT / NT2)
#define VBW      75            // vb row stride (float2 / float units)
#define NGRP     11            // ceil(TH / 6) vpass rowgroups
#define VTASKS   (NGRP * HTW)  // 814
#define MAINB    256           // (1024/64)*(1024/64)

// smem layout (bytes), 16B-aligned
#define OFF_F01   0                       // float2[HT]      43808
#define OFF_F2    43808                   // float [HT]      21904
#define OFF_VB01  65712                   // float2[64*75]   38400
#define OFF_VB2   104112                  // float [64*75]   19200
#define SMEM_TOTAL 123312

struct GW { float w[WS]; };

// ---------------- scratch (static device globals; no allocation) ----------------
__device__ uint2 g_muY2[KK * NPIX / 4];   // per-pixel muYs (shifted) as 4 halfs (16MB)
__device__ uint2 g_cs2[NPIX / 4];         // per-pixel cs_map as 4 halfs (2MB)
__device__ uint2 g_mx2[NPIX / 4];         // per-pixel muXs (shifted) as 4 halfs (2MB)
__device__ float g_lY_part[KK * MAINB];
__device__ float g_lG[KK];
__device__ float g_q_part[MAINB];
__device__ int   g_done1 = 0;
__device__ int   g_done2 = 0;

// ======================= separable blur helpers =======================
// Vertical: 6 consecutive output rows per task, 16 taps -> 2.67 loads/output.
// 814 tasks (11 rowgroups x 74 cols) over 1024 threads.
__device__ __forceinline__ void vpass6(const float2* __restrict__ f01,
                                       const float* __restrict__ f2,
                                       float2* __restrict__ vb01,
                                       float* __restrict__ vb2,
                                       const float* gw, int tid) {
    if (tid < VTASKS) {
        int g = tid / HTW, c = tid - g * HTW;
        int r0 = g * 6;
        float ax[6], ay[6], az[6];
#pragma unroll
        for (int i = 0; i < 6; i++) { ax[i] = 0.f; ay[i] = 0.f; az[i] = 0.f; }
        const float2* p01 = f01 + r0 * HTW + c;
        const float*  p2  = f2  + r0 * HTW + c;
#pragma unroll
        for (int j = 0; j < 16; j++) {
            if (r0 + j < HTH) {
                float2 v = p01[j * HTW];
                float  z = p2[j * HTW];
#pragma unroll
                for (int i = 0; i < 6; i++) {
                    if (i <= j && j - i <= 10) {
                        float gg = gw[j - i];
                        ax[i] += gg * v.x; ay[i] += gg * v.y; az[i] += gg * z;
                    }
                }
            }
        }
#pragma unroll
        for (int i = 0; i < 6; i++) {
            int r = r0 + i;
            if (r < TH) {
                vb01[r * VBW + c] = make_float2(ax[i], ay[i]);
                vb2[r * VBW + c] = az[i];
            }
        }
    }
}

// Horizontal: lane = row (strides conflict-free), 4 cols/thread.
__device__ __forceinline__ void hpass(const float2* __restrict__ vb01,
                                      const float* __restrict__ vb2,
                                      const float* gw, int row, int x0, float3* out) {
    float ax[4], ay[4], az[4];
#pragma unroll
    for (int i = 0; i < 4; i++) { ax[i] = 0.f; ay[i] = 0.f; az[i] = 0.f; }
    const float2* p01 = vb01 + row * VBW + x0;
    const float*  p2  = vb2  + row * VBW + x0;
#pragma unroll
    for (int j = 0; j < 14; j++) {
        float2 v = p01[j];
        float  z = p2[j];
#pragma unroll
        for (int i = 0; i < 4; i++) {
            if (i <= j && j - i <= 10) {
                float gg = gw[j - i];
                ax[i] += gg * v.x; ay[i] += gg * v.y; az[i] += gg * z;
            }
        }
    }
#pragma unroll
    for (int i = 0; i < 4; i++) out[i] = make_float3(ax[i], ay[i], az[i]);
}

// Pack-write: load bunch k tile (shifted), build (s, s², s·o') fields.
__device__ __forceinline__ void pack_write(const float* __restrict__ bb,
                                           const int* goff, const __half2* h01,
                                           const __half2* h2p,
                                           float2* __restrict__ s_f01,
                                           float* __restrict__ s_f2, int tid) {
#pragma unroll
    for (int i = 0; i < NLOAD; i++) {
        int e = tid + i * NT2;
        if (e < HT) {
            int o = goff[i];
            float v0 = -0.5f, v1 = -0.5f, v2 = -0.5f;
            if (o >= 0) {
                v0 = bb[o] - 0.5f; v1 = bb[NPIX + o] - 0.5f; v2 = bb[2 * NPIX + o] - 0.5f;
            }
            float2 o01 = __half22float2(h01[i]);
            float  o2  = __half2float((i & 1) ? __high2half(h2p[i >> 1])
                                              : __low2half(h2p[i >> 1]));
            s_f01[e] = make_float2((v0 + v1 + v2) * (1.f / 3.f),
                                   (v0 * v0 + v1 * v1 + v2 * v2) * (1.f / 3.f));
            s_f2[e]  = (v0 * o01.x + v1 * o01.y + v2 * o2) * (1.f / 3.f);
        }
    }
}

__device__ __forceinline__ uint2 pack4h(float a, float b, float c, float d) {
    __half2 p0 = __floats2half2_rn(a, b);
    __half2 p1 = __floats2half2_rn(c, d);
    uint2 u;
    u.x = *(const unsigned int*)&p0;
    u.y = *(const unsigned int*)&p1;
    return u;
}

// ======================= k1: stats pass =======================
// Shifted domain v' = v - 0.5 (exact; reference zero-pads raw => padded v' = -0.5).
__global__ __launch_bounds__(NT2, 1) void mef_stats_k(
    const float* __restrict__ img,
    const float* __restrict__ bunch,
    float* __restrict__ patch_out,
    GW gwp)
{
    extern __shared__ char sm[];
    float2* s_f01  = (float2*)(sm + OFF_F01);
    float*  s_f2   = (float*)(sm + OFF_F2);
    float2* s_vb01 = (float2*)(sm + OFF_VB01);
    float*  s_vb2  = (float*)(sm + OFF_VB2);
    __shared__ float s_ly[32 * KK];     // per-warp per-k lY partials
    __shared__ float qw[32];
    const float* gw = gwp.w;

    int tid = threadIdx.x;
    int lane = tid & 31;
    int wid = tid >> 5;
    int row = tid & 63;          // hpass: output row
    int x0c = (tid >> 6) * 4;    // hpass: 4 consecutive output cols
    int bx = blockIdx.x, by = blockIdx.y;
    int T  = by * gridDim.x + bx;    // tile id 0..255
    int gx0 = bx * TW - RAD, gy0 = by * TH - RAD;

    // per-thread halo state: global offsets + output-image channels (half regs)
    int goff[NLOAD];
    __half2 h01[NLOAD];          // (o0', o1')
    __half2 h2p[3];              // o2' packed pairs
#pragma unroll
    for (int i = 0; i < 3; i++) h2p[i] = __halves2half2(__float2half(0.f), __float2half(0.f));

#pragma unroll
    for (int i = 0; i < NLOAD; i++) {
        int e = tid + i * NT2;
        float o0 = -0.5f, o1 = -0.5f, o2 = -0.5f;
        int o = -2;
        if (e < HT) {
            int hy = e / HTW, hx = e - hy * HTW;
            int gy = gy0 + hy, gx = gx0 + hx;
            o = (((unsigned)gy < HH) && ((unsigned)gx < WW)) ? gy * WW + gx : -1;
            if (o >= 0) {
                o0 = img[o] - 0.5f; o1 = img[NPIX + o] - 0.5f; o2 = img[2 * NPIX + o] - 0.5f;
            }
            s_f01[e] = make_float2((o0 + o1 + o2) * (1.f / 3.f),
                                   (o0 * o0 + o1 * o1 + o2 * o2) * (1.f / 3.f));
            s_f2[e] = 0.f;
        }
        goff[i] = o;
        h01[i] = __floats2half2_rn(o0, o1);
        __half h2v = __float2half_rn(o2);
        if (i & 1) h2p[i >> 1] = __halves2half2(__low2half(h2p[i >> 1]), h2v);
        else       h2p[i >> 1] = __halves2half2(h2v, __high2half(h2p[i >> 1]));
    }
    __syncthreads();

    vpass6(s_f01, s_f2, s_vb01, s_vb2, gw, tid);
    __syncthreads();                 // vb ready; pack free
    float3 xo[4];
    hpass(s_vb01, s_vb2, gw, row, x0c, xo);
    float muXs[4], sX2[4];
#pragma unroll
    for (int i = 0; i < 4; i++) { muXs[i] = xo[i].x; sX2[i] = xo[i].y - muXs[i] * muXs[i]; }

    // write pack for k=0 while other warps still in hpass (same barrier interval)
    pack_write(bunch, goff, h01, h2p, s_f01, s_f2, tid);
    __syncthreads();                 // pack(0) ready; vb consumed

    float best[4], bestXY[4];
    int pidx[4];
#pragma unroll
    for (int i = 0; i < 4; i++) { best[i] = -1e30f; bestXY[i] = 0.f; pidx[i] = 0; }

    for (int k = 0; k < KK; k++) {
        vpass6(s_f01, s_f2, s_vb01, s_vb2, gw, tid);
        __syncthreads();             // vb ready; pack free
        float3 yo[4];
        hpass(s_vb01, s_vb2, gw, row, x0c, yo);

#pragma unroll
        for (int i = 0; i < 4; i++) {
            float muYs = yo[i].x;
            float sY2 = yo[i].y - muYs * muYs;
            float sXY = yo[i].z - muXs[i] * muYs;
            if (sY2 > best[i]) { best[i] = sY2; bestXY[i] = sXY; pidx[i] = k; }
        }
        // store muYs for blend pass (half, tile-private coalesced layout)
        g_muY2[(size_t)(T * KK + k) * NT2 + tid] =
            pack4h(yo[0].x, yo[1].x, yo[2].x, yo[3].x);
        // per-warp lY partial (exact: tiles partition image)
        float lsum = yo[0].x + yo[1].x + yo[2].x + yo[3].x;
#pragma unroll
        for (int o = 16; o > 0; o >>= 1) lsum += __shfl_xor_sync(0xffffffffu, lsum, o);
        if (lane == 0) s_ly[wid * KK + k] = lsum;

        // prefetch + pack next exposure, overlapping hpass/stat issue stream
        if (k < KK - 1)
            pack_write(bunch + (size_t)(3 * (k + 1)) * NPIX, goff, h01, h2p,
                       s_f01, s_f2, tid);
        __syncthreads();             // pack(k+1) ready; vb consumed; s_ly visible
    }

    // ---- epilogue ----
    // lY partials: fold 32 warps per k (8 threads, deterministic serial order)
    if (tid < KK) {
        float v = 0.f;
#pragma unroll
        for (int w = 0; w < 32; w++) v += s_ly[w * KK + tid];
        g_lY_part[tid * MAINB + T] = v;
    }

    // cs + muXs (half) and patch staging
    float* sidx = (float*)s_vb01;   // staging: 64 x 64 floats (16KB)
    float csv[4];
#pragma unroll
    for (int i = 0; i < 4; i++) {
        csv[i] = (2.f * bestXY[i] + 9e-4f) /
                 fmaxf(sX2[i] + best[i] + 9e-4f, 1e-6f);   // C2 = 0.03^2
        sidx[row * 64 + x0c + i] = (float)pidx[i];
    }
    g_cs2[(size_t)T * NT2 + tid] = pack4h(csv[0], csv[1], csv[2], csv[3]);
    g_mx2[(size_t)T * NT2 + tid] = pack4h(muXs[0], muXs[1], muXs[2], muXs[3]);

    __syncthreads();
    if (patch_out) {
        // scalar stores: patch_out base is only 4B-aligned (out + 1).
        int rr = tid >> 4, cc = (tid & 15) * 4;
        float* dst = &patch_out[(by * TH + rr) * WW + bx * TW + cc];
        const float* src = &sidx[tid * 4];
        dst[0] = src[0]; dst[1] = src[1]; dst[2] = src[2]; dst[3] = src[3];
    }

    // ---- last block: fold lY partials -> lG ----
    __shared__ int isLast;
    if (tid == 0) {
        __threadfence();
        isLast = (atomicAdd(&g_done1, 1) == MAINB - 1);
    }
    __syncthreads();
    if (isLast) {
        __threadfence();
        for (int k = 0; k < KK; k++) {
            float s = (tid < MAINB) ? g_lY_part[k * MAINB + tid] : 0.f;
#pragma unroll
            for (int o = 16; o > 0; o >>= 1) s += __shfl_xor_sync(0xffffffffu, s, o);
            if (lane == 0) qw[wid] = s;
            __syncthreads();
            if (tid < 32) {
                float v = qw[tid];
#pragma unroll
                for (int o = 16; o > 0; o >>= 1) v += __shfl_xor_sync(0xffffffffu, v, o);
                if (tid == 0) {
                    double d = (double)v / (double)NPIX;   // = mean(muYs) = lY - 0.5
                    g_lG[k] = (float)exp(-(d * d) / 0.08); // DENOM_G = 2*0.2^2
                }
            }
            __syncthreads();
        }
        if (tid == 0) g_done1 = 0;   // self-reset for next graph replay
    }
}

// ======================= k2: luminance blend + q =======================
__global__ __launch_bounds__(NT2) void mef_blend_k(float* __restrict__ q_out) {
    __shared__ float s_lG[KK];
    __shared__ float qw[32];
    int tid = threadIdx.x;
    int lane = tid & 31, wid = tid >> 5;
    int T = blockIdx.x;

    if (tid < KK) s_lG[tid] = g_lG[tid];
    __syncthreads();

    float num[4], den[4];
#pragma unroll
    for (int i = 0; i < 4; i++) { num[i] = 0.f; den[i] = 0.f; }

#pragma unroll
    for (int k = 0; k < KK; k++) {
        uint2 u = g_muY2[(size_t)(T * KK + k) * NT2 + tid];
        __half2 pa = *(const __half2*)&u.x;
        __half2 pb = *(const __half2*)&u.y;
        float2 f0 = __half22float2(pa);
        float2 f1 = __half22float2(pb);
        float m[4] = {f0.x, f0.y, f1.x, f1.y};
        float lGk = s_lG[k];
#pragma unroll
        for (int i = 0; i < 4; i++) {
            float wgt = lGk * __expf(-(m[i] * m[i]) * (1.f / 0.08f));   // DENOM_L
            num[i] += wgt * (m[i] + 0.5f);
            den[i] += wgt;
        }
    }

    uint2 cu = g_cs2[(size_t)T * NT2 + tid];
    uint2 mu = g_mx2[(size_t)T * NT2 + tid];
    float2 c0 = __half22float2(*(const __half2*)&cu.x);
    float2 c1 = __half22float2(*(const __half2*)&cu.y);
    float2 x0 = __half22float2(*(const __half2*)&mu.x);
    float2 x1 = __half22float2(*(const __half2*)&mu.y);
    float cs[4] = {c0.x, c0.y, c1.x, c1.y};
    float mx[4] = {x0.x, x0.y, x1.x, x1.y};

    float qsum = 0.f;
#pragma unroll
    for (int i = 0; i < 4; i++) {
        float muX  = mx[i] + 0.5f;
        float muYb = num[i] / den[i];
        float l = (2.f * muX * muYb + 1e-4f) /
                  fmaxf(muX * muX + muYb * muYb + 1e-4f, 1e-6f);   // C1 = 0.01^2
        qsum += l * cs[i];
    }

#pragma unroll
    for (int o = 16; o > 0; o >>= 1) qsum += __shfl_xor_sync(0xffffffffu, qsum, o);
    if (lane == 0) qw[wid] = qsum;
    __syncthreads();
    if (tid < 32) {
        float v = qw[tid];
#pragma unroll
        for (int o = 16; o > 0; o >>= 1) v += __shfl_xor_sync(0xffffffffu, v, o);
        if (tid == 0) g_q_part[T] = v;
    }

    __shared__ int isLast;
    if (tid == 0) {
        __threadfence();
        isLast = (atomicAdd(&g_done2, 1) == MAINB - 1);
    }
    __syncthreads();
    if (isLast) {
        __threadfence();
        float s = (tid < MAINB) ? g_q_part[tid] : 0.f;
#pragma unroll
        for (int o = 16; o > 0; o >>= 1) s += __shfl_xor_sync(0xffffffffu, s, o);
        if (lane == 0) qw[wid] = s;
        __syncthreads();
        if (tid < 32) {
            float v = qw[tid];
#pragma unroll
            for (int o = 16; o > 0; o >>= 1) v += __shfl_xor_sync(0xffffffffu, v, o);
            if (tid == 0) {
                if (q_out) q_out[0] = v / (float)NPIX;
                g_done2 = 0;
            }
        }
    }
}

// ---------------- launch ----------------
extern "C" void kernel_launch(void* const* d_in, const int* in_sizes, int n_in,
                              void* d_out, int out_size) {
    const float* a = (const float*)d_in[0];
    const float* b = (const float*)d_in[1];
    const float* img;
    const float* bunch;
    if (in_sizes[0] > in_sizes[1]) { bunch = a; img = b; }
    else                           { img = a;  bunch = b; }

    float* out = (float*)d_out;
    float* qdst = nullptr;
    float* patch = nullptr;
    if (out_size >= NPIX + 1)      { qdst = out; patch = out + 1; }
    else if (out_size == NPIX)     { patch = out; }
    else                           { qdst = out; }

    // host-side double-precision gaussian window
    GW gwp;
    {
        double t[WS], s = 0.0;
        double sg = (double)WS / 6.0;
        for (int i = 0; i < WS; i++) {
            double d = (double)(i - RAD);
            t[i] = exp(-(d * d) / (2.0 * sg * sg));
            s += t[i];
        }
        for (int i = 0; i < WS; i++) gwp.w[i] = (float)(t[i] / s);
    }

    static bool attr_set = false;
    if (!attr_set) {
        cudaFuncSetAttribute(mef_stats_k, cudaFuncAttributeMaxDynamicSharedMemorySize, SMEM_TOTAL);
        attr_set = true;
    }

    mef_stats_k<<<dim3(WW / TW, HH / TH), NT2, SMEM_TOTAL>>>(img, bunch, patch, gwp);
    mef_blend_k<<<MAINB, NT2>>>(qdst);
}